// round 13
// baseline (speedup 1.0000x reference)
#include <cuda_runtime.h>
#include <cuda_fp16.h>
#include <cstdint>

// MeshGNN collapsed to per-row MLP (vertex dim degenerate: h starts uniform
// across the 12 vertices and adjacency is row-stochastic with identical row
// sums s, so A@h = s*h at every layer):
//   H0 = X(32768x384) @ Wt(384x256) + bt
//   Hl = relu(s*(Hl-1 @ Wg[l]) + bg[l]),  l=1..4
//   Out[b,v,:] = Tm[v,:] + (H4 @ Wo + bo)[b,:]
// FP8 e4m3 mma.sync.m16n8k32 with F16 ACCUMULATE (halves acc registers ->
// 64 regs/thread -> 1024-thread CTA, 32 warps, occ 50%, 8 warps/SMSP).
// Weights pre-arranged into exact mma fragment layout by the prep kernel and
// loaded via coalesced LDG.128 (no weight SMEM, no cp.async, no block syncs).
// 8 row-groups of 128 threads sync via named barriers and drift freely.

#define MTILE   256
#define NTHR    1024
#define NCHUNK  11

__device__ __align__(128) unsigned char g_wf[NCHUNK * 32768]; // B frags, fragment-ordered

// ---------------- PTX helpers ----------------
__device__ __forceinline__ uint32_t smem_u32(const void* p) {
    uint32_t a;
    asm("{ .reg .u64 t; cvta.to.shared.u64 t, %1; cvt.u32.u64 %0, t; }" : "=r"(a) : "l"(p));
    return a;
}
#define LDSM4(r0,r1,r2,r3,ad) \
    asm volatile("ldmatrix.sync.aligned.m8n8.x4.shared.b16 {%0,%1,%2,%3}, [%4];" \
        : "=r"(r0),"=r"(r1),"=r"(r2),"=r"(r3) : "r"(ad))
#define MMAFP8H(d,a,b0,b1) \
    asm volatile("mma.sync.aligned.m16n8k32.row.col.f16.e4m3.e4m3.f16 " \
        "{%0,%1}, {%2,%3,%4,%5}, {%6,%7}, {%0,%1};" \
        : "+r"((d)[0]),"+r"((d)[1]) \
        : "r"((a)[0]),"r"((a)[1]),"r"((a)[2]),"r"((a)[3]), "r"(b0),"r"(b1))
#define STS16(ad,v)  asm volatile("st.shared.b16 [%0], %1;" :: "r"(ad), "h"(v) : "memory")
#define STS128(ad,a,b,c,d) asm volatile("st.shared.v4.b32 [%0], {%1,%2,%3,%4};" \
        :: "r"(ad), "r"(a),"r"(b),"r"(c),"r"(d) : "memory")
#define BARW(id) asm volatile("bar.sync %0, 128;" :: "r"((id)) : "memory")
#define PACK_E4(d,lo,hi) asm("cvt.rn.satfinite.e4m3x2.f32 %0, %1, %2;" : "=h"(d) : "f"(hi), "f"(lo))

__device__ __forceinline__ uint32_t pack4_e4m3(float a, float b, float c, float d) {
    uint16_t lo, hi;
    PACK_E4(lo, a, b);
    PACK_E4(hi, c, d);
    return (uint32_t)lo | ((uint32_t)hi << 16);
}
__device__ __forceinline__ float f16_lo(uint32_t v) { return __half2float(__ushort_as_half((uint16_t)(v & 0xffff))); }
__device__ __forceinline__ float f16_hi(uint32_t v) { return __half2float(__ushort_as_half((uint16_t)(v >> 16))); }

// ---------------- SMEM layout (~168 KB, one CTA per SM) ----------------
#define OFF_HS    0          // 256 rows x 256B (256 e4m3, swizzled)      64KB
#define OFF_XS    65536      // 3 x 32KB e4m3 X tiles (256 x 128)         96KB
#define OFF_DP    65536      //   (reused after GEMM1) [256][12] f32     12KB
#define OFF_DFIN  77824      //   (reused) [256][3] f32                   3KB
#define OFF_BIAS  163840     // 1280 fp32: bt(256) + bg(1024)
#define OFF_WO    168960     // 771 fp32 (Wo with anti-conflict skew)
#define OFF_TM    172048     // 36 fp32
#define SMEM_SZ   172192

// ---------------- prep: B fragments in mma register layout ----------------
// One warp per (chunk c, col-group wn). Stage 64 n-rows x 128 k e4m3 into a
// swizzled SMEM tile, then run the main loop's exact ldmatrix and store each
// lane's 4 regs to g_wf[((c*4+wn)*16 + kk*4 + np)*512 + lane*16].
extern "C" __global__ void mesh_prep(const float* __restrict__ Wt,
                                     const float* __restrict__ Wg) {
    __shared__ __align__(128) unsigned char tile[8192];
    int c = blockIdx.x >> 2, wn = blockIdx.x & 3;
    int lane = threadIdx.x;
    const float* src; int kb0;
    if (c < 3) { src = Wt; kb0 = c * 128; }
    else { int l = (c - 3) >> 1, h = (c - 3) & 1; src = Wg + l * 65536; kb0 = h * 128; }
    for (int i = 0; i < 16; i++) {
        int u = lane + 32 * i;            // 0..511 16B units
        int nl = u >> 3, cc = u & 7;
        int n = wn * 64 + nl;
        int kbase = kb0 + cc * 16;
        float f[16];
        #pragma unroll
        for (int j = 0; j < 16; j++) f[j] = src[(size_t)(kbase + j) * 256 + n];
        uint32_t pk[4];
        #pragma unroll
        for (int q = 0; q < 4; q++) pk[q] = pack4_e4m3(f[4*q], f[4*q+1], f[4*q+2], f[4*q+3]);
        int off = nl * 128 + (((cc ^ (nl & 7)) & 7) << 4);
        *(uint4*)(tile + off) = *(uint4*)pk;
    }
    __syncwarp();
    uint32_t tb = smem_u32(tile);
    const int b_nrow = ((lane >> 4) << 3) + (lane & 7);
    const int b_cco  = (lane >> 3) & 1;
    for (int kk = 0; kk < 4; kk++)
        for (int np = 0; np < 4; np++) {
            int nl = np * 16 + b_nrow;
            int cc = kk * 2 + b_cco;
            uint32_t ad = tb + nl * 128 + (((cc ^ (nl & 7)) & 7) << 4);
            uint32_t r0, r1, r2, r3;
            LDSM4(r0, r1, r2, r3, ad);
            uint4 v = make_uint4(r0, r1, r2, r3);
            *(uint4*)(g_wf + (size_t)(((c * 4 + wn) * 16 + kk * 4 + np) * 512) + lane * 16) = v;
        }
}

// ---------------- compute one K=128 chunk (warp tile 32x64, f16 acc) -------
__device__ __forceinline__ void compute_chunk(
    uint32_t aBase, int aStride, int ccBase, const uint4* __restrict__ bSrc,
    int wm, int lane, uint32_t (&uacc)[2][8][2])
{
    const int a_mrow = (lane & 7) + ((lane >> 3) & 1) * 8;
    const int a_cco  = lane >> 4;
    #pragma unroll
    for (int kk = 0; kk < 4; kk++) {
        uint4 bb[4];
        #pragma unroll
        for (int np = 0; np < 4; np++) bb[np] = bSrc[kk * 128 + np * 32 + lane];
        uint32_t a[2][4];
        #pragma unroll
        for (int mi = 0; mi < 2; mi++) {
            int m  = wm * 32 + mi * 16 + a_mrow;
            int cc = ccBase + kk * 2 + a_cco;
            uint32_t ad = aBase + m * aStride + (((cc & ~7) | ((cc ^ (m & 7)) & 7)) << 4);
            LDSM4(a[mi][0], a[mi][1], a[mi][2], a[mi][3], ad);
        }
        #pragma unroll
        for (int mi = 0; mi < 2; mi++)
            #pragma unroll
            for (int ni = 0; ni < 8; ni++) {
                uint32_t b0 = (ni & 1) ? bb[ni >> 1].z : bb[ni >> 1].x;
                uint32_t b1 = (ni & 1) ? bb[ni >> 1].w : bb[ni >> 1].y;
                MMAFP8H(uacc[mi][ni], a[mi], b0, b1);
            }
    }
}

// ---------------- main ----------------
extern "C" __global__ void __launch_bounds__(NTHR)
mesh_main(const float* __restrict__ X,  const float* __restrict__ bt,
          const float* __restrict__ bg, const float* __restrict__ Wo,
          const float* __restrict__ bo, const float* __restrict__ Adj,
          const float* __restrict__ Tm, float* __restrict__ Out)
{
    extern __shared__ __align__(1024) char smem[];
    const uint32_t sb = smem_u32(smem);
    const int tid = threadIdx.x, lane = tid & 31, wid = tid >> 5;
    const int wm = wid >> 2, wn = wid & 3;   // 8 contiguous row-groups of 128 thr
    const int gl = tid & 127;
    const int row0 = blockIdx.x * MTILE;

    float* biasS = (float*)(smem + OFF_BIAS);
    float* WoS   = (float*)(smem + OFF_WO);
    float* TmS   = (float*)(smem + OFF_TM);

    // params
    if (tid < 256) biasS[tid] = bt[tid];
    biasS[256 + tid] = bg[tid];
    if (tid < 768) { int k = tid / 3; WoS[tid + (k >> 6)] = Wo[tid]; }
    if (tid < 36) TmS[tid] = Tm[tid];
    float s = 0.0f;
    #pragma unroll
    for (int m = 0; m < 12; m++) s += Adj[m];

    // prologue: convert ALL X (3 chunks of K=128) to e4m3 swizzled tiles
    {
        const int xrow = tid >> 2, xseg = tid & 3;   // 256 rows x 4 segs
        const float* xp = X + (size_t)(row0 + xrow) * 384 + xseg * 32;
        #pragma unroll
        for (int c3 = 0; c3 < 3; c3++) {
            float4 v[8];
            #pragma unroll
            for (int q = 0; q < 8; q++) v[q] = ((const float4*)(xp + c3 * 128))[q];
            uint32_t pk[8];
            #pragma unroll
            for (int q = 0; q < 8; q++) pk[q] = pack4_e4m3(v[q].x, v[q].y, v[q].z, v[q].w);
            uint32_t base = sb + OFF_XS + c3 * 32768 + xrow * 128;
            int cg0 = xseg * 2;
            STS128(base + (((cg0       ^ (xrow & 7)) & 7) << 4), pk[0], pk[1], pk[2], pk[3]);
            STS128(base + ((((cg0 + 1) ^ (xrow & 7)) & 7) << 4), pk[4], pk[5], pk[6], pk[7]);
        }
    }
    __syncthreads();   // the ONLY block-wide barrier

    uint32_t uacc[2][8][2];
    #pragma unroll
    for (int i = 0; i < 2; i++)
        #pragma unroll
        for (int j = 0; j < 8; j++) { uacc[i][j][0] = 0u; uacc[i][j][1] = 0u; }

    for (int g = 0; g < NCHUNK; g++) {
        const uint4* bSrc = (const uint4*)(g_wf + (size_t)(g * 4 + wn) * 8192);
        if (g < 3) compute_chunk(sb + OFF_XS + g * 32768, 128, 0, bSrc, wm, lane, uacc);
        else       compute_chunk(sb + OFF_HS, 256, ((g - 3) & 1) * 8, bSrc, wm, lane, uacc);

        int p = (g == 2) ? 0 : (g >= 4 && (g & 1) == 0) ? (g >> 1) - 1 : -1;
        if (p >= 0) {
            if (p >= 1) BARW(wm + 1);   // group's HS reads done before overwrite
            const float* bp = biasS + p * 256;
            float dp[4][3];
            if (p == 4)
                #pragma unroll
                for (int r = 0; r < 4; r++) dp[r][0] = dp[r][1] = dp[r][2] = 0.0f;
            #pragma unroll
            for (int mi = 0; mi < 2; mi++) {
                int r0 = wm * 32 + mi * 16 + (lane >> 2);
                #pragma unroll
                for (int ni = 0; ni < 8; ni++) {
                    int n0 = wn * 64 + ni * 8 + 2 * (lane & 3);
                    float2 bv = *(const float2*)(bp + n0);
                    float v00, v01, v10, v11;
                    if (p == 0) {
                        v00 = f16_lo(uacc[mi][ni][0]) + bv.x;
                        v01 = f16_hi(uacc[mi][ni][0]) + bv.y;
                        v10 = f16_lo(uacc[mi][ni][1]) + bv.x;
                        v11 = f16_hi(uacc[mi][ni][1]) + bv.y;
                    } else {
                        v00 = fmaxf(fmaf(s, f16_lo(uacc[mi][ni][0]), bv.x), 0.f);
                        v01 = fmaxf(fmaf(s, f16_hi(uacc[mi][ni][0]), bv.y), 0.f);
                        v10 = fmaxf(fmaf(s, f16_lo(uacc[mi][ni][1]), bv.x), 0.f);
                        v11 = fmaxf(fmaf(s, f16_hi(uacc[mi][ni][1]), bv.y), 0.f);
                    }
                    if (p < 4) {
                        uint16_t p0, p1;
                        PACK_E4(p0, v00, v01);
                        PACK_E4(p1, v10, v11);
                        int cB = wn * 32 + ni * 4 + (lane & 3);      // b16 col = n0/2
                        int cg = cB >> 3;
                        int sg = (cg & 8) | ((cg ^ (r0 & 7)) & 7);
                        uint32_t ad = sb + OFF_HS + r0 * 256 + (sg << 4) + ((cB & 7) << 1);
                        STS16(ad, p0);
                        STS16(ad + 8 * 256, p1);
                    } else {
                        const float* wp = WoS + n0 * 3 + (n0 >> 6);
                        #pragma unroll
                        for (int j = 0; j < 3; j++) {
                            dp[mi*2+0][j] = fmaf(v00, wp[j], fmaf(v01, wp[3+j], dp[mi*2+0][j]));
                            dp[mi*2+1][j] = fmaf(v10, wp[j], fmaf(v11, wp[3+j], dp[mi*2+1][j]));
                        }
                    }
                    uacc[mi][ni][0] = 0u;
                    uacc[mi][ni][1] = 0u;
                }
            }
            if (p < 4) {
                BARW(wm + 1);   // group's HS writes visible before next layer reads
            } else {
                // out-pass within row-group: d = H4 @ Wo + bo; Out = Tm + d
                float* DPs = (float*)(smem + OFF_DP);
                #pragma unroll
                for (int r = 0; r < 4; r++)
                    #pragma unroll
                    for (int j = 0; j < 3; j++) {
                        dp[r][j] += __shfl_xor_sync(0xffffffffu, dp[r][j], 1);
                        dp[r][j] += __shfl_xor_sync(0xffffffffu, dp[r][j], 2);
                    }
                if ((lane & 3) == 0) {
                    #pragma unroll
                    for (int mi = 0; mi < 2; mi++) {
                        int r = wm * 32 + mi * 16 + (lane >> 2);
                        #pragma unroll
                        for (int j = 0; j < 3; j++) {
                            DPs[r * 12 + wn * 3 + j]       = dp[mi*2+0][j];
                            DPs[(r + 8) * 12 + wn * 3 + j] = dp[mi*2+1][j];
                        }
                    }
                }
                BARW(wm + 1);
                float* DF = (float*)(smem + OFF_DFIN);
                if (gl < 96) {
                    int rl = gl / 3, j = gl - rl * 3;
                    int r = wm * 32 + rl;
                    float d = bo[j] + DPs[r*12 + j] + DPs[r*12 + 3 + j]
                                    + DPs[r*12 + 6 + j] + DPs[r*12 + 9 + j];
                    DF[r * 3 + j] = d;
                }
                BARW(wm + 1);
                float* op = Out + (size_t)row0 * 36 + wm * 1152;
                #pragma unroll
                for (int it = 0; it < 9; it++) {      // 32 rows x 36 per group
                    int i = gl + it * 128;
                    int rl = i / 36, rem = i - rl * 36;
                    op[i] = TmS[rem] + DF[(wm * 32 + rl) * 3 + rem % 3];
                }
            }
        }
    }
}

extern "C" void kernel_launch(void* const* d_in, const int* in_sizes, int n_in,
                              void* d_out, int out_size) {
    const float* X   = (const float*)d_in[0];
    const float* Wt  = (const float*)d_in[1];
    const float* bt  = (const float*)d_in[2];
    const float* Wg  = (const float*)d_in[3];
    const float* bg  = (const float*)d_in[4];
    const float* Wo  = (const float*)d_in[5];
    const float* bo  = (const float*)d_in[6];
    const float* Adj = (const float*)d_in[7];
    const float* Tm  = (const float*)d_in[8];
    float* Out = (float*)d_out;

    mesh_prep<<<NCHUNK * 4, 32>>>(Wt, Wg);
    cudaFuncSetAttribute(mesh_main, cudaFuncAttributeMaxDynamicSharedMemorySize, SMEM_SZ);
    mesh_main<<<32768 / MTILE, NTHR, SMEM_SZ>>>(X, bt, bg, Wo, bo, Adj, Tm, Out);
}

// round 14
// speedup vs baseline: 3.1010x; 3.1010x over previous
#include <cuda_runtime.h>
#include <cuda_fp16.h>
#include <cstdint>

// MeshGNN collapsed to per-row MLP (vertex dim degenerate: h starts uniform
// across the 12 vertices and adjacency is row-stochastic with identical row
// sums s, so A@h = s*h at every layer):
//   H0 = X(32768x384) @ Wt(384x256) + bt
//   Hl = relu(s*(Hl-1 @ Wg[l]) + bg[l]),  l=1..4
//   Out[b,v,:] = Tm[v,:] + (H4 @ Wo + bo)[b,:]
// FP8 e4m3 mma.sync.m16n8k32 with F16 ACCUMULATE. launch_bounds(512,2):
// two co-resident 512-thread CTAs per SM (8 warps/SMSP, 64 regs/thread, no
// spill) in ONE wave (grid 256, 2/SM). Weights pre-arranged into exact mma
// fragment layout by the prep kernel and fetched via coalesced LDG.128
// (no weight SMEM/cp.async; the two CTAs share the same L1/L2 lines).
// 4 row-groups of 128 threads per CTA sync via named barriers.

#define MTILE   128
#define NTHR    512
#define NCHUNK  11

__device__ __align__(128) unsigned char g_wf[NCHUNK * 32768]; // B frags, fragment-ordered

// ---------------- PTX helpers ----------------
__device__ __forceinline__ uint32_t smem_u32(const void* p) {
    uint32_t a;
    asm("{ .reg .u64 t; cvta.to.shared.u64 t, %1; cvt.u32.u64 %0, t; }" : "=r"(a) : "l"(p));
    return a;
}
#define LDSM4(r0,r1,r2,r3,ad) \
    asm volatile("ldmatrix.sync.aligned.m8n8.x4.shared.b16 {%0,%1,%2,%3}, [%4];" \
        : "=r"(r0),"=r"(r1),"=r"(r2),"=r"(r3) : "r"(ad))
#define MMAFP8H(d,a,b0,b1) \
    asm volatile("mma.sync.aligned.m16n8k32.row.col.f16.e4m3.e4m3.f16 " \
        "{%0,%1}, {%2,%3,%4,%5}, {%6,%7}, {%0,%1};" \
        : "+r"((d)[0]),"+r"((d)[1]) \
        : "r"((a)[0]),"r"((a)[1]),"r"((a)[2]),"r"((a)[3]), "r"(b0),"r"(b1))
#define STS16(ad,v)  asm volatile("st.shared.b16 [%0], %1;" :: "r"(ad), "h"(v) : "memory")
#define STS128(ad,a,b,c,d) asm volatile("st.shared.v4.b32 [%0], {%1,%2,%3,%4};" \
        :: "r"(ad), "r"(a),"r"(b),"r"(c),"r"(d) : "memory")
#define BARW(id) asm volatile("bar.sync %0, 128;" :: "r"((id)) : "memory")
#define PACK_E4(d,lo,hi) asm("cvt.rn.satfinite.e4m3x2.f32 %0, %1, %2;" : "=h"(d) : "f"(hi), "f"(lo))

__device__ __forceinline__ uint32_t pack4_e4m3(float a, float b, float c, float d) {
    uint16_t lo, hi;
    PACK_E4(lo, a, b);
    PACK_E4(hi, c, d);
    return (uint32_t)lo | ((uint32_t)hi << 16);
}
__device__ __forceinline__ float f16_lo(uint32_t v) { return __half2float(__ushort_as_half((uint16_t)(v & 0xffff))); }
__device__ __forceinline__ float f16_hi(uint32_t v) { return __half2float(__ushort_as_half((uint16_t)(v >> 16))); }

// ---------------- SMEM layout (~90 KB per CTA, 2 CTAs/SM) ----------------
#define OFF_HS    0          // 128 rows x 256B (256 e4m3, swizzled)      32KB
#define OFF_XS    32768      // 3 x 16KB e4m3 X tiles (128 x 128)         48KB
#define OFF_DP    32768      //   (reused after GEMM1) [128][12] f32       6KB
#define OFF_DFIN  40960      //   (reused) [128][3] f32                  1.5KB
#define OFF_BIAS  81920      // 1280 fp32: bt(256) + bg(1024)
#define OFF_WO    87040      // 771 fp32 (Wo with anti-conflict skew)
#define OFF_TM    90128      // 36 fp32
#define SMEM_SZ   90272

// ---------------- prep: B fragments in mma register layout ----------------
// One warp per (chunk c, col-group wn). Stage 64 n-rows x 128 k e4m3 into a
// swizzled SMEM tile, then run the main loop's exact ldmatrix and store each
// lane's 4 regs to g_wf[((c*4+wn)*16 + kk*4 + np)*512 + lane*16].
extern "C" __global__ void mesh_prep(const float* __restrict__ Wt,
                                     const float* __restrict__ Wg) {
    __shared__ __align__(128) unsigned char tile[8192];
    int c = blockIdx.x >> 2, wn = blockIdx.x & 3;
    int lane = threadIdx.x;
    const float* src; int kb0;
    if (c < 3) { src = Wt; kb0 = c * 128; }
    else { int l = (c - 3) >> 1, h = (c - 3) & 1; src = Wg + l * 65536; kb0 = h * 128; }
    for (int i = 0; i < 16; i++) {
        int u = lane + 32 * i;            // 0..511 16B units
        int nl = u >> 3, cc = u & 7;
        int n = wn * 64 + nl;
        int kbase = kb0 + cc * 16;
        float f[16];
        #pragma unroll
        for (int j = 0; j < 16; j++) f[j] = src[(size_t)(kbase + j) * 256 + n];
        uint32_t pk[4];
        #pragma unroll
        for (int q = 0; q < 4; q++) pk[q] = pack4_e4m3(f[4*q], f[4*q+1], f[4*q+2], f[4*q+3]);
        int off = nl * 128 + (((cc ^ (nl & 7)) & 7) << 4);
        *(uint4*)(tile + off) = *(uint4*)pk;
    }
    __syncwarp();
    uint32_t tb = smem_u32(tile);
    const int b_nrow = ((lane >> 4) << 3) + (lane & 7);
    const int b_cco  = (lane >> 3) & 1;
    for (int kk = 0; kk < 4; kk++)
        for (int np = 0; np < 4; np++) {
            int nl = np * 16 + b_nrow;
            int cc = kk * 2 + b_cco;
            uint32_t ad = tb + nl * 128 + (((cc ^ (nl & 7)) & 7) << 4);
            uint32_t r0, r1, r2, r3;
            LDSM4(r0, r1, r2, r3, ad);
            uint4 v = make_uint4(r0, r1, r2, r3);
            *(uint4*)(g_wf + (size_t)(((c * 4 + wn) * 16 + kk * 4 + np) * 512) + lane * 16) = v;
        }
}

// ---------------- compute one K=128 chunk (warp tile 32x64, f16 acc) -------
__device__ __forceinline__ void compute_chunk(
    uint32_t aBase, int aStride, int ccBase, const uint4* __restrict__ bSrc,
    int wm, int lane, uint32_t (&uacc)[2][8][2])
{
    const int a_mrow = (lane & 7) + ((lane >> 3) & 1) * 8;
    const int a_cco  = lane >> 4;
    #pragma unroll
    for (int kk = 0; kk < 4; kk++) {
        uint4 bb[4];
        #pragma unroll
        for (int np = 0; np < 4; np++) bb[np] = bSrc[kk * 128 + np * 32 + lane];
        uint32_t a[2][4];
        #pragma unroll
        for (int mi = 0; mi < 2; mi++) {
            int m  = wm * 32 + mi * 16 + a_mrow;
            int cc = ccBase + kk * 2 + a_cco;
            uint32_t ad = aBase + m * aStride + (((cc & ~7) | ((cc ^ (m & 7)) & 7)) << 4);
            LDSM4(a[mi][0], a[mi][1], a[mi][2], a[mi][3], ad);
        }
        #pragma unroll
        for (int mi = 0; mi < 2; mi++)
            #pragma unroll
            for (int ni = 0; ni < 8; ni++) {
                uint32_t b0 = (ni & 1) ? bb[ni >> 1].z : bb[ni >> 1].x;
                uint32_t b1 = (ni & 1) ? bb[ni >> 1].w : bb[ni >> 1].y;
                MMAFP8H(uacc[mi][ni], a[mi], b0, b1);
            }
    }
}

// ---------------- main ----------------
extern "C" __global__ void __launch_bounds__(NTHR, 2)
mesh_main(const float* __restrict__ X,  const float* __restrict__ bt,
          const float* __restrict__ bg, const float* __restrict__ Wo,
          const float* __restrict__ bo, const float* __restrict__ Adj,
          const float* __restrict__ Tm, float* __restrict__ Out)
{
    extern __shared__ __align__(1024) char smem[];
    const uint32_t sb = smem_u32(smem);
    const int tid = threadIdx.x, lane = tid & 31, wid = tid >> 5;
    const int wm = wid >> 2, wn = wid & 3;   // 4 contiguous row-groups of 128 thr
    const int gl = tid & 127;
    const int row0 = blockIdx.x * MTILE;

    float* biasS = (float*)(smem + OFF_BIAS);
    float* WoS   = (float*)(smem + OFF_WO);
    float* TmS   = (float*)(smem + OFF_TM);

    // params
    if (tid < 256) biasS[tid] = bt[tid];
    biasS[256 + tid] = bg[tid];
    if (tid < 512) biasS[768 + tid] = bg[512 + tid];
    for (int i = tid; i < 768; i += NTHR) { int k = i / 3; WoS[i + (k >> 6)] = Wo[i]; }
    if (tid < 36) TmS[tid] = Tm[tid];
    float s = 0.0f;
    #pragma unroll
    for (int m = 0; m < 12; m++) s += Adj[m];

    // prologue: convert ALL X (3 chunks of K=128) to e4m3 swizzled tiles
    {
        const int xrow = tid >> 2, xseg = tid & 3;
        const float* xp = X + (size_t)(row0 + xrow) * 384 + xseg * 32;
        #pragma unroll
        for (int c3 = 0; c3 < 3; c3++) {
            float4 v[8];
            #pragma unroll
            for (int q = 0; q < 8; q++) v[q] = ((const float4*)(xp + c3 * 128))[q];
            uint32_t pk[8];
            #pragma unroll
            for (int q = 0; q < 8; q++) pk[q] = pack4_e4m3(v[q].x, v[q].y, v[q].z, v[q].w);
            uint32_t base = sb + OFF_XS + c3 * 16384 + xrow * 128;
            int cg0 = xseg * 2;
            STS128(base + (((cg0       ^ (xrow & 7)) & 7) << 4), pk[0], pk[1], pk[2], pk[3]);
            STS128(base + ((((cg0 + 1) ^ (xrow & 7)) & 7) << 4), pk[4], pk[5], pk[6], pk[7]);
        }
    }
    __syncthreads();   // the ONLY block-wide barrier

    uint32_t uacc[2][8][2];
    #pragma unroll
    for (int i = 0; i < 2; i++)
        #pragma unroll
        for (int j = 0; j < 8; j++) { uacc[i][j][0] = 0u; uacc[i][j][1] = 0u; }

    for (int g = 0; g < NCHUNK; g++) {
        const uint4* bSrc = (const uint4*)(g_wf + (size_t)(g * 4 + wn) * 8192);
        if (g < 3) compute_chunk(sb + OFF_XS + g * 16384, 128, 0, bSrc, wm, lane, uacc);
        else       compute_chunk(sb + OFF_HS, 256, ((g - 3) & 1) * 8, bSrc, wm, lane, uacc);

        int p = (g == 2) ? 0 : (g >= 4 && (g & 1) == 0) ? (g >> 1) - 1 : -1;
        if (p >= 0) {
            if (p >= 1) BARW(wm + 1);   // group's HS reads done before overwrite
            const float* bp = biasS + p * 256;
            float dp[4][3];
            if (p == 4)
                #pragma unroll
                for (int r = 0; r < 4; r++) dp[r][0] = dp[r][1] = dp[r][2] = 0.0f;
            #pragma unroll
            for (int mi = 0; mi < 2; mi++) {
                int r0 = wm * 32 + mi * 16 + (lane >> 2);
                #pragma unroll
                for (int ni = 0; ni < 8; ni++) {
                    int n0 = wn * 64 + ni * 8 + 2 * (lane & 3);
                    float2 bv = *(const float2*)(bp + n0);
                    float v00, v01, v10, v11;
                    if (p == 0) {
                        v00 = f16_lo(uacc[mi][ni][0]) + bv.x;
                        v01 = f16_hi(uacc[mi][ni][0]) + bv.y;
                        v10 = f16_lo(uacc[mi][ni][1]) + bv.x;
                        v11 = f16_hi(uacc[mi][ni][1]) + bv.y;
                    } else {
                        v00 = fmaxf(fmaf(s, f16_lo(uacc[mi][ni][0]), bv.x), 0.f);
                        v01 = fmaxf(fmaf(s, f16_hi(uacc[mi][ni][0]), bv.y), 0.f);
                        v10 = fmaxf(fmaf(s, f16_lo(uacc[mi][ni][1]), bv.x), 0.f);
                        v11 = fmaxf(fmaf(s, f16_hi(uacc[mi][ni][1]), bv.y), 0.f);
                    }
                    if (p < 4) {
                        uint16_t p0, p1;
                        PACK_E4(p0, v00, v01);
                        PACK_E4(p1, v10, v11);
                        int cB = wn * 32 + ni * 4 + (lane & 3);      // b16 col = n0/2
                        int cg = cB >> 3;
                        int sg = (cg & 8) | ((cg ^ (r0 & 7)) & 7);
                        uint32_t ad = sb + OFF_HS + r0 * 256 + (sg << 4) + ((cB & 7) << 1);
                        STS16(ad, p0);
                        STS16(ad + 8 * 256, p1);
                    } else {
                        const float* wp = WoS + n0 * 3 + (n0 >> 6);
                        #pragma unroll
                        for (int j = 0; j < 3; j++) {
                            dp[mi*2+0][j] = fmaf(v00, wp[j], fmaf(v01, wp[3+j], dp[mi*2+0][j]));
                            dp[mi*2+1][j] = fmaf(v10, wp[j], fmaf(v11, wp[3+j], dp[mi*2+1][j]));
                        }
                    }
                    uacc[mi][ni][0] = 0u;
                    uacc[mi][ni][1] = 0u;
                }
            }
            if (p < 4) {
                BARW(wm + 1);   // group's HS writes visible before next layer reads
            } else {
                // out-pass within row-group: d = H4 @ Wo + bo; Out = Tm + d
                float* DPs = (float*)(smem + OFF_DP);
                #pragma unroll
                for (int r = 0; r < 4; r++)
                    #pragma unroll
                    for (int j = 0; j < 3; j++) {
                        dp[r][j] += __shfl_xor_sync(0xffffffffu, dp[r][j], 1);
                        dp[r][j] += __shfl_xor_sync(0xffffffffu, dp[r][j], 2);
                    }
                if ((lane & 3) == 0) {
                    #pragma unroll
                    for (int mi = 0; mi < 2; mi++) {
                        int r = wm * 32 + mi * 16 + (lane >> 2);
                        #pragma unroll
                        for (int j = 0; j < 3; j++) {
                            DPs[r * 12 + wn * 3 + j]       = dp[mi*2+0][j];
                            DPs[(r + 8) * 12 + wn * 3 + j] = dp[mi*2+1][j];
                        }
                    }
                }
                BARW(wm + 1);
                float* DF = (float*)(smem + OFF_DFIN);
                if (gl < 96) {
                    int rl = gl / 3, j = gl - rl * 3;
                    int r = wm * 32 + rl;
                    float d = bo[j] + DPs[r*12 + j] + DPs[r*12 + 3 + j]
                                    + DPs[r*12 + 6 + j] + DPs[r*12 + 9 + j];
                    DF[r * 3 + j] = d;
                }
                BARW(wm + 1);
                float* op = Out + (size_t)row0 * 36 + wm * 1152;
                #pragma unroll
                for (int it = 0; it < 9; it++) {      // 32 rows x 36 per group
                    int i = gl + it * 128;
                    int rl = i / 36, rem = i - rl * 36;
                    op[i] = TmS[rem] + DF[(wm * 32 + rl) * 3 + rem % 3];
                }
            }
        }
    }
}

extern "C" void kernel_launch(void* const* d_in, const int* in_sizes, int n_in,
                              void* d_out, int out_size) {
    const float* X   = (const float*)d_in[0];
    const float* Wt  = (const float*)d_in[1];
    const float* bt  = (const float*)d_in[2];
    const float* Wg  = (const float*)d_in[3];
    const float* bg  = (const float*)d_in[4];
    const float* Wo  = (const float*)d_in[5];
    const float* bo  = (const float*)d_in[6];
    const float* Adj = (const float*)d_in[7];
    const float* Tm  = (const float*)d_in[8];
    float* Out = (float*)d_out;

    mesh_prep<<<NCHUNK * 4, 32>>>(Wt, Wg);
    cudaFuncSetAttribute(mesh_main, cudaFuncAttributeMaxDynamicSharedMemorySize, SMEM_SZ);
    mesh_main<<<32768 / MTILE, NTHR, SMEM_SZ>>>(X, bt, bg, Wo, bo, Adj, Tm, Out);
}

// round 15
// speedup vs baseline: 4.3651x; 1.4076x over previous
#include <cuda_runtime.h>
#include <cuda_bf16.h>
#include <cstdint>

// MeshGNN collapsed to per-row MLP (vertex dim degenerate: h starts uniform
// across the 12 vertices and adjacency is row-stochastic with identical row
// sums s, so A@h = s*h at every layer):
//   H0 = X(32768x384) @ Wt(384x256) + bt
//   Hl = relu(s*(Hl-1 @ Wg[l]) + bg[l]),  l=1..4
//   Out[b,v,:] = Tm[v,:] + (H4 @ Wo + bo)[b,:]
// FP8 e4m3 mma.sync.m16n8k32 (f32 acc), 11 K=128 chunks. Overhead-stripped:
//  - warp-private cp.async weight staging (each warp stages only the 8KB
//    quarter it ldmatrix'es; per-thread wait groups; NO per-chunk block sync)
//  - row-group (4 warps / 128 thr) named barriers only around epilogues
//  - within-unit k-permutation pi(s)=4(s&1)+(s>>1) applied to BOTH A and B
//    (exact: mma sums over k) so epilogue H stores become 16x STS.32.

#define MTILE   128
#define NTHR    512
#define NCHUNK  11

__device__ __align__(128) unsigned char g_wb[NCHUNK * 32768]; // e4m3 [N=256][K=128] swizzled+k-perm

// ---------------- PTX helpers ----------------
__device__ __forceinline__ uint32_t smem_u32(const void* p) {
    uint32_t a;
    asm("{ .reg .u64 t; cvta.to.shared.u64 t, %1; cvt.u32.u64 %0, t; }" : "=r"(a) : "l"(p));
    return a;
}
#define LDSM4(r0,r1,r2,r3,ad) \
    asm volatile("ldmatrix.sync.aligned.m8n8.x4.shared.b16 {%0,%1,%2,%3}, [%4];" \
        : "=r"(r0),"=r"(r1),"=r"(r2),"=r"(r3) : "r"(ad))
#define MMAFP8(d,a,b0,b1) \
    asm volatile("mma.sync.aligned.m16n8k32.row.col.f32.e4m3.e4m3.f32 " \
        "{%0,%1,%2,%3}, {%4,%5,%6,%7}, {%8,%9}, {%0,%1,%2,%3};" \
        : "+f"((d)[0]),"+f"((d)[1]),"+f"((d)[2]),"+f"((d)[3]) \
        : "r"((a)[0]),"r"((a)[1]),"r"((a)[2]),"r"((a)[3]), "r"(b0),"r"(b1))
#define STS32(ad,v)  asm volatile("st.shared.b32 [%0], %1;" :: "r"(ad), "r"(v) : "memory")
#define STS128(ad,a,b,c,d) asm volatile("st.shared.v4.b32 [%0], {%1,%2,%3,%4};" \
        :: "r"(ad), "r"(a),"r"(b),"r"(c),"r"(d) : "memory")
#define CPA16(dst,src) asm volatile("cp.async.ca.shared.global [%0], [%1], 16;" \
        :: "r"(dst), "l"(src) : "memory")
#define CPA_COMMIT() asm volatile("cp.async.commit_group;" ::: "memory")
#define CPA_WAIT1()  asm volatile("cp.async.wait_group 1;" ::: "memory")
#define BARW(id) asm volatile("bar.sync %0, 128;" :: "r"((id)) : "memory")
#define PACK_E4(d,lo,hi) asm("cvt.rn.satfinite.e4m3x2.f32 %0, %1, %2;" : "=h"(d) : "f"(hi), "f"(lo))

__device__ __forceinline__ uint32_t pack4_e4m3(float a, float b, float c, float d) {
    uint16_t lo, hi;
    PACK_E4(lo, a, b);
    PACK_E4(hi, c, d);
    return (uint32_t)lo | ((uint32_t)hi << 16);
}

// ---------------- SMEM layout ----------------
#define OFF_HS    0          // 128 rows x 256B (256 e4m3, swizzled)      32KB
#define OFF_WS    32768      // 2 x 32KB weight chunk buffers             64KB
#define OFF_XS    98304      // 3 x 16KB e4m3 X tiles (128 x 128)         48KB
#define OFF_DP    98304      //   (reused after GEMM1) [128][12] f32       6KB
#define OFF_DFIN  106496     //   (reused) [128][3] f32                  1.5KB
#define OFF_BIAS  147456     // 1280 fp32: bt(256) + bg(1024)
#define OFF_WO    152576     // 771 fp32 (Wo with anti-conflict skew)
#define OFF_TM    155664     // 36 fp32
#define SMEM_SZ   155808

// ---------------- prep: e4m3 [N][K=128] swizzled + k-permuted chunks -------
// chunk c<3: Wt k-rows c*128..+128; c>=3: Wg[(c-3)/2], k-rows ((c-3)%2)*128..+128
// unit (n, cc): 16B; 32-bit word j holds k-pairs (j, j+4) -> slots s carry
// k-pair pi(s)=4(s&1)+(s>>1). Same permutation applied to X and H tiles.
extern "C" __global__ void mesh_prep(const float* __restrict__ Wt,
                                     const float* __restrict__ Wg) {
    int c = blockIdx.x >> 3;
    int u = ((blockIdx.x & 7) << 8) + threadIdx.x;   // 0..2047 16B units
    int n = u >> 3, cc = u & 7;
    const float* src; int kbase;
    if (c < 3) { src = Wt; kbase = c * 128 + cc * 16; }
    else { int l = (c - 3) >> 1, h = (c - 3) & 1; src = Wg + l * 65536; kbase = h * 128 + cc * 16; }
    float f[16];
    #pragma unroll
    for (int j = 0; j < 16; j++) f[j] = src[(size_t)(kbase + j) * 256 + n];  // B[n][k] = W[k][n]
    uint32_t pk[4];
    #pragma unroll
    for (int j = 0; j < 4; j++) pk[j] = pack4_e4m3(f[2*j], f[2*j+1], f[2*j+8], f[2*j+9]);
    int off = n * 128 + (((cc ^ (n & 7)) & 7) << 4);
    *(uint4*)(g_wb + (size_t)c * 32768 + off) = *(uint4*)pk;
}

// ---------------- compute one K=128 chunk (warp tile 32x64) ----------------
__device__ __forceinline__ void compute_chunk(
    uint32_t aBase, int aStride, int ccBase, uint32_t bBase,
    int wm, int wn, int lane, float (&acc)[2][8][4])
{
    const int a_mrow = (lane & 7) + ((lane >> 3) & 1) * 8;
    const int a_cco  = lane >> 4;
    const int b_nrow = ((lane >> 4) << 3) + (lane & 7);
    const int b_cco  = (lane >> 3) & 1;
    #pragma unroll
    for (int kk = 0; kk < 4; kk++) {
        uint32_t a[2][4];
        #pragma unroll
        for (int mi = 0; mi < 2; mi++) {
            int m  = wm * 32 + mi * 16 + a_mrow;
            int cc = ccBase + kk * 2 + a_cco;
            uint32_t ad = aBase + m * aStride + (((cc & ~7) | ((cc ^ (m & 7)) & 7)) << 4);
            LDSM4(a[mi][0], a[mi][1], a[mi][2], a[mi][3], ad);
        }
        uint32_t bb[4][4];
        #pragma unroll
        for (int np = 0; np < 4; np++) {
            int n  = wn * 64 + np * 16 + b_nrow;
            int cc = kk * 2 + b_cco;
            uint32_t ad = bBase + n * 128 + (((cc ^ (n & 7)) & 7) << 4);
            LDSM4(bb[np][0], bb[np][1], bb[np][2], bb[np][3], ad);
        }
        #pragma unroll
        for (int mi = 0; mi < 2; mi++)
            #pragma unroll
            for (int ni = 0; ni < 8; ni++)
                MMAFP8(acc[mi][ni], a[mi], bb[ni >> 1][(ni & 1) * 2], bb[ni >> 1][(ni & 1) * 2 + 1]);
    }
}

// warp-private staging of this warp's B quarter (8KB) of chunk c
__device__ __forceinline__ void stage_quarter(uint32_t sb, int c, int wn, int lane) {
    size_t gs = __cvta_generic_to_global((const char*)g_wb)
              + (size_t)c * 32768 + wn * 8192 + lane * 16;
    uint32_t dst = sb + OFF_WS + (c & 1) * 32768 + wn * 8192 + lane * 16;
    #pragma unroll
    for (int q = 0; q < 16; q++) CPA16(dst + q * 512, gs + q * 512);
}

// ---------------- main ----------------
extern "C" __global__ void __launch_bounds__(NTHR)
mesh_main(const float* __restrict__ X,  const float* __restrict__ bt,
          const float* __restrict__ bg, const float* __restrict__ Wo,
          const float* __restrict__ bo, const float* __restrict__ Adj,
          const float* __restrict__ Tm, float* __restrict__ Out)
{
    extern __shared__ __align__(1024) char smem[];
    const uint32_t sb = smem_u32(smem);
    const int tid = threadIdx.x, lane = tid & 31, wid = tid >> 5;
    const int wm = wid >> 2, wn = wid & 3;   // 4 contiguous row-groups of 128 thr
    const int gl = tid & 127;
    const int row0 = blockIdx.x * MTILE;

    float* biasS = (float*)(smem + OFF_BIAS);
    float* WoS   = (float*)(smem + OFF_WO);
    float* TmS   = (float*)(smem + OFF_TM);

    // params
    if (tid < 256) biasS[tid] = bt[tid];
    biasS[256 + tid] = bg[tid];
    if (tid < 512) biasS[768 + tid] = bg[512 + tid];
    for (int i = tid; i < 768; i += NTHR) { int k = i / 3; WoS[i + (k >> 6)] = Wo[i]; }
    if (tid < 36) TmS[tid] = Tm[tid];
    float s = 0.0f;
    #pragma unroll
    for (int m = 0; m < 12; m++) s += Adj[m];

    // stage own quarter of chunk 0
    stage_quarter(sb, 0, wn, lane);
    CPA_COMMIT();

    // prologue: convert ALL X (3 chunks of K=128) to e4m3 swizzled+k-perm tiles
    {
        const int xrow = tid >> 2, xseg = tid & 3;   // 4 segs of 32 floats (2 units)
        const float* xp = X + (size_t)(row0 + xrow) * 384 + xseg * 32;
        #pragma unroll
        for (int c3 = 0; c3 < 3; c3++) {
            float4 v[8];
            #pragma unroll
            for (int q = 0; q < 8; q++) v[q] = ((const float4*)(xp + c3 * 128))[q];
            uint32_t pk[8];
            // unit0: words j = kpairs (j, j+4); floats (2j,2j+1, 2j+8,2j+9)
            pk[0] = pack4_e4m3(v[0].x, v[0].y, v[2].x, v[2].y);
            pk[1] = pack4_e4m3(v[0].z, v[0].w, v[2].z, v[2].w);
            pk[2] = pack4_e4m3(v[1].x, v[1].y, v[3].x, v[3].y);
            pk[3] = pack4_e4m3(v[1].z, v[1].w, v[3].z, v[3].w);
            pk[4] = pack4_e4m3(v[4].x, v[4].y, v[6].x, v[6].y);
            pk[5] = pack4_e4m3(v[4].z, v[4].w, v[6].z, v[6].w);
            pk[6] = pack4_e4m3(v[5].x, v[5].y, v[7].x, v[7].y);
            pk[7] = pack4_e4m3(v[5].z, v[5].w, v[7].z, v[7].w);
            uint32_t base = sb + OFF_XS + c3 * 16384 + xrow * 128;
            int cg0 = xseg * 2;
            STS128(base + (((cg0       ^ (xrow & 7)) & 7) << 4), pk[0], pk[1], pk[2], pk[3]);
            STS128(base + ((((cg0 + 1) ^ (xrow & 7)) & 7) << 4), pk[4], pk[5], pk[6], pk[7]);
        }
    }
    __syncthreads();   // the ONLY block-wide barrier (X tiles + params visible)

    float acc[2][8][4];
    #pragma unroll
    for (int i = 0; i < 2; i++)
        #pragma unroll
        for (int j = 0; j < 8; j++)
            #pragma unroll
            for (int q = 0; q < 4; q++) acc[i][j][q] = 0.0f;

    for (int g = 0; g < NCHUNK; g++) {
        if (g + 1 < NCHUNK) stage_quarter(sb, g + 1, wn, lane);
        CPA_COMMIT();
        CPA_WAIT1();   // chunk g's quarter resident (per-thread groups)

        uint32_t bBase = sb + OFF_WS + (g & 1) * 32768;
        if (g < 3) compute_chunk(sb + OFF_XS + g * 16384, 128, 0, bBase, wm, wn, lane, acc);
        else       compute_chunk(sb + OFF_HS, 256, ((g - 3) & 1) * 8, bBase, wm, wn, lane, acc);

        int p = (g == 2) ? 0 : (g >= 4 && (g & 1) == 0) ? (g >> 1) - 1 : -1;
        if (p >= 0) {
            if (p >= 1) BARW(wm + 1);   // group's HS reads done before overwrite
            const float* bp = biasS + p * 256;
            const float scale = (p == 0) ? 1.0f : s;
            if (p < 4) {
                #pragma unroll
                for (int mi = 0; mi < 2; mi++) {
                    int r0 = wm * 32 + mi * 16 + (lane >> 2);
                    #pragma unroll
                    for (int t = 0; t < 4; t++) {
                        uint16_t pe[2], po[2];
                        #pragma unroll
                        for (int h = 0; h < 2; h++) {
                            int ni = 2 * t + h;
                            int n0 = wn * 64 + ni * 8 + 2 * (lane & 3);
                            float2 bv = *(const float2*)(bp + n0);
                            float v00 = fmaf(scale, acc[mi][ni][0], bv.x);
                            float v01 = fmaf(scale, acc[mi][ni][1], bv.y);
                            float v10 = fmaf(scale, acc[mi][ni][2], bv.x);
                            float v11 = fmaf(scale, acc[mi][ni][3], bv.y);
                            if (p > 0) {
                                v00 = fmaxf(v00, 0.f); v01 = fmaxf(v01, 0.f);
                                v10 = fmaxf(v10, 0.f); v11 = fmaxf(v11, 0.f);
                            }
                            PACK_E4(pe[h], v00, v01);
                            PACK_E4(po[h], v10, v11);
                            acc[mi][ni][0] = acc[mi][ni][1] = acc[mi][ni][2] = acc[mi][ni][3] = 0.0f;
                        }
                        uint32_t w0 = (uint32_t)pe[0] | ((uint32_t)pe[1] << 16);
                        uint32_t w1 = (uint32_t)po[0] | ((uint32_t)po[1] << 16);
                        int cu = wn * 4 + t;
                        int sg = (cu & 8) | ((cu ^ (r0 & 7)) & 7);
                        uint32_t ad = sb + OFF_HS + r0 * 256 + (sg << 4) + ((lane & 3) << 2);
                        STS32(ad, w0);
                        STS32(ad + 8 * 256, w1);
                    }
                }
                BARW(wm + 1);   // group's HS writes visible before next layer reads
            } else {
                // final: fold output GEMM, then Out = Tm + d (all group-local)
                float dp[4][3];
                #pragma unroll
                for (int r = 0; r < 4; r++) dp[r][0] = dp[r][1] = dp[r][2] = 0.0f;
                #pragma unroll
                for (int mi = 0; mi < 2; mi++) {
                    #pragma unroll
                    for (int ni = 0; ni < 8; ni++) {
                        int n0 = wn * 64 + ni * 8 + 2 * (lane & 3);
                        float2 bv = *(const float2*)(bp + n0);
                        float v00 = fmaxf(fmaf(s, acc[mi][ni][0], bv.x), 0.f);
                        float v01 = fmaxf(fmaf(s, acc[mi][ni][1], bv.y), 0.f);
                        float v10 = fmaxf(fmaf(s, acc[mi][ni][2], bv.x), 0.f);
                        float v11 = fmaxf(fmaf(s, acc[mi][ni][3], bv.y), 0.f);
                        const float* wp = WoS + n0 * 3 + (n0 >> 6);
                        #pragma unroll
                        for (int j = 0; j < 3; j++) {
                            dp[mi*2+0][j] = fmaf(v00, wp[j], fmaf(v01, wp[3+j], dp[mi*2+0][j]));
                            dp[mi*2+1][j] = fmaf(v10, wp[j], fmaf(v11, wp[3+j], dp[mi*2+1][j]));
                        }
                    }
                }
                float* DPs = (float*)(smem + OFF_DP);
                #pragma unroll
                for (int r = 0; r < 4; r++)
                    #pragma unroll
                    for (int j = 0; j < 3; j++) {
                        dp[r][j] += __shfl_xor_sync(0xffffffffu, dp[r][j], 1);
                        dp[r][j] += __shfl_xor_sync(0xffffffffu, dp[r][j], 2);
                    }
                if ((lane & 3) == 0) {
                    #pragma unroll
                    for (int mi = 0; mi < 2; mi++) {
                        int r = wm * 32 + mi * 16 + (lane >> 2);
                        #pragma unroll
                        for (int j = 0; j < 3; j++) {
                            DPs[r * 12 + wn * 3 + j]       = dp[mi*2+0][j];
                            DPs[(r + 8) * 12 + wn * 3 + j] = dp[mi*2+1][j];
                        }
                    }
                }
                BARW(wm + 1);
                float* DF = (float*)(smem + OFF_DFIN);
                if (gl < 96) {
                    int rl = gl / 3, j = gl - rl * 3;
                    int r = wm * 32 + rl;
                    float d = bo[j] + DPs[r*12 + j] + DPs[r*12 + 3 + j]
                                    + DPs[r*12 + 6 + j] + DPs[r*12 + 9 + j];
                    DF[r * 3 + j] = d;
                }
                BARW(wm + 1);
                float* op = Out + (size_t)row0 * 36 + wm * 1152;
                #pragma unroll
                for (int it = 0; it < 9; it++) {      // 32 rows x 36 per group
                    int i = gl + it * 128;
                    int rl = i / 36, rem = i - rl * 36;
                    op[i] = TmS[rem] + DF[(wm * 32 + rl) * 3 + rem % 3];
                }
            }
        }
    }
}

extern "C" void kernel_launch(void* const* d_in, const int* in_sizes, int n_in,
                              void* d_out, int out_size) {
    const float* X   = (const float*)d_in[0];
    const float* Wt  = (const float*)d_in[1];
    const float* bt  = (const float*)d_in[2];
    const float* Wg  = (const float*)d_in[3];
    const float* bg  = (const float*)d_in[4];
    const float* Wo  = (const float*)d_in[5];
    const float* bo  = (const float*)d_in[6];
    const float* Adj = (const float*)d_in[7];
    const float* Tm  = (const float*)d_in[8];
    float* Out = (float*)d_out;

    mesh_prep<<<NCHUNK * 8, 256>>>(Wt, Wg);
    cudaFuncSetAttribute(mesh_main, cudaFuncAttributeMaxDynamicSharedMemorySize, SMEM_SZ);
    mesh_main<<<32768 / MTILE, NTHR, SMEM_SZ>>>(X, bt, bg, Wo, bo, Adj, Tm, Out);
}